// round 9
// baseline (speedup 1.0000x reference)
#include <cuda_runtime.h>
#include <cuda_fp16.h>
#include <cstdint>

static constexpr int BATCH = 65536;
static constexpr int KD    = 512;
static constexpr int ND    = 512;

static constexpr int BM = 64;
static constexpr int BN = 256;
static constexpr int BK = 32;            // 32 fp16 = 64B B-rows
static constexpr int NKITER = KD / BK;   // 16
static constexpr int STAGES = 3;

static constexpr int A_BYTES    = BM * KD * 2;                  // 65536 resident
static constexpr int B_STAGE    = BN * BK * 2;                  // 16384
static constexpr int SMEM_TOTAL = A_BYTES + STAGES * B_STAGE;   // 114688 (x2 = 224KB/SM)

// ---------------- fp16 W scratch, K-blocked [kt][n][32] (no allocs allowed) ----------------
__device__ __align__(256) __half g_wb[ND * KD];

// ---------------- helpers ----------------
static __device__ __forceinline__ uint32_t smem_u32(const void* p) {
    uint32_t a;
    asm("{ .reg .u64 t; cvta.to.shared.u64 t, %1; cvt.u32.u64 %0, t; }"
        : "=r"(a) : "l"(p));
    return a;
}

__device__ __forceinline__ void cp16(uint32_t dst, const void* src) {
    asm volatile("cp.async.cg.shared.global [%0], [%1], 16;"
                 :: "r"(dst), "l"(src) : "memory");
}
__device__ __forceinline__ void cp_commit() {
    asm volatile("cp.async.commit_group;" ::: "memory");
}
template <int N>
__device__ __forceinline__ void cp_wait() {
    asm volatile("cp.async.wait_group %0;" :: "n"(N) : "memory");
}

__device__ __forceinline__ void ldsm4(uint32_t& r0, uint32_t& r1, uint32_t& r2,
                                      uint32_t& r3, uint32_t addr) {
    asm volatile("ldmatrix.sync.aligned.m8n8.x4.shared.b16 {%0,%1,%2,%3}, [%4];"
                 : "=r"(r0), "=r"(r1), "=r"(r2), "=r"(r3) : "r"(addr));
}

__device__ __forceinline__ void mma16816(float* d, const uint32_t* a, const uint32_t* b) {
    asm volatile(
        "mma.sync.aligned.m16n8k16.row.col.f32.f16.f16.f32 "
        "{%0,%1,%2,%3}, {%4,%5,%6,%7}, {%8,%9}, {%0,%1,%2,%3};"
        : "+f"(d[0]), "+f"(d[1]), "+f"(d[2]), "+f"(d[3])
        : "r"(a[0]), "r"(a[1]), "r"(a[2]), "r"(a[3]), "r"(b[0]), "r"(b[1]));
}

// ---------------- W prepass: fp32 row-major -> fp16 K-blocked [kt][n][32] ----------------
__global__ void __launch_bounds__(256) cvt_w_kernel(const float* __restrict__ s) {
    size_t idx = (size_t)blockIdx.x * 256 + threadIdx.x;   // one float4 each
    int n  = (int)(idx >> 7);
    int c4 = (int)(idx & 127);
    float4 v = reinterpret_cast<const float4*>(s)[idx];
    __half2 h0 = __floats2half2_rn(v.x, v.y);
    __half2 h1 = __floats2half2_rn(v.z, v.w);
    uint2 u;
    u.x = *reinterpret_cast<uint32_t*>(&h0);
    u.y = *reinterpret_cast<uint32_t*>(&h1);
    int kt = c4 >> 3, ci = c4 & 7;
    *reinterpret_cast<uint2*>(g_wb + (size_t)kt * (ND * BK) + (size_t)n * BK + ci * 4) = u;
}

// ---------------- fused GEMM: 256 threads, 2 CTAs/SM (16 warps), warp tile 64x32 ----------
// A smem: 64 rows x 1024B; 16B chunk c (0..63) of row r at
//   r*1024 + 16*((c & ~7) + ((c&7) ^ (r&7)))
// B stage: 256 rows x 64B; chunk c (0..3) of row r at r*64 + 16*(c ^ ((r>>1)&3))
__global__ void __launch_bounds__(256, 2)
gemm_fused_kernel(const float* __restrict__ X, const float* __restrict__ Bv,
                  float* __restrict__ Y) {
    extern __shared__ __align__(1024) char smem[];
    const uint32_t sa  = smem_u32(smem);      // A resident
    const uint32_t sbb = sa + A_BYTES;        // B stages

    const int tid  = threadIdx.x;
    const int wid  = tid >> 5;                // 0..7 -> N offset wid*32
    const int lane = tid & 31;

    const int bm = blockIdx.x >> 1;
    const int bn = blockIdx.x & 1;
    const int row0 = bm * BM;
    const int col0 = bn * BN;

    // ---- B staging: 1024 16B-chunks per stage, 256 threads x 4 ----
    auto stageB = [&](int kt, int slot) {
        const uint32_t base = sbb + slot * B_STAGE;
        const __half* src = g_wb + (size_t)kt * (ND * BK) + (size_t)col0 * BK;
#pragma unroll
        for (int i = 0; i < 4; i++) {
            int idx = tid + i * 256;
            int r = idx >> 2, c = idx & 3;
            uint32_t dst = base + (uint32_t)(r * 64 + ((c ^ ((r >> 1) & 3)) << 4));
            cp16(dst, src + (size_t)r * BK + c * 8);
        }
    };

    stageB(0, 0); cp_commit();
    stageB(1, 1); cp_commit();

    // ---- A prologue: convert x fp32 -> fp16 resident tile (4096 chunks / 256 thr) ----
    {
        const float* xs = X + (size_t)row0 * KD;
#pragma unroll
        for (int i = 0; i < 16; i++) {
            int idx = tid + i * 256;
            int r = idx >> 6, c = idx & 63;
            const float4* sp = reinterpret_cast<const float4*>(xs + (size_t)r * KD + c * 8);
            float4 v0 = sp[0], v1 = sp[1];
            __half2 h0 = __floats2half2_rn(v0.x, v0.y);
            __half2 h1 = __floats2half2_rn(v0.z, v0.w);
            __half2 h2 = __floats2half2_rn(v1.x, v1.y);
            __half2 h3 = __floats2half2_rn(v1.z, v1.w);
            uint4 u;
            u.x = *reinterpret_cast<uint32_t*>(&h0);
            u.y = *reinterpret_cast<uint32_t*>(&h1);
            u.z = *reinterpret_cast<uint32_t*>(&h2);
            u.w = *reinterpret_cast<uint32_t*>(&h3);
            uint32_t off = (uint32_t)(r * 1024 + (((c & ~7) + ((c & 7) ^ (r & 7))) << 4));
            *reinterpret_cast<uint4*>(smem + off) = u;
        }
    }
    __syncthreads();

    // ---- fragment addressing ----
    const int lr  = lane & 15;
    const int lc  = lane >> 4;               // 0/1 -> +16B k-chunk
    const int sw7 = lane & 7;                // A xor
    const int bsw = (lr >> 1) & 3;           // B xor

    uint32_t aRow[4], bRow[2];
#pragma unroll
    for (int mt = 0; mt < 4; mt++)
        aRow[mt] = sa + (uint32_t)((mt * 16 + lr) * 1024);
#pragma unroll
    for (int np = 0; np < 2; np++)
        bRow[np] = (uint32_t)((wid * 32 + np * 16 + lr) * 64);

    float acc[4][4][4];
#pragma unroll
    for (int i = 0; i < 4; i++)
#pragma unroll
        for (int j = 0; j < 4; j++)
#pragma unroll
            for (int e = 0; e < 4; e++) acc[i][j][e] = 0.0f;

    for (int kt = 0; kt < NKITER; kt++) {
        cp_wait<1>();
        __syncthreads();
        if (kt + 2 < NKITER) stageB(kt + 2, (kt + 2) % STAGES);
        cp_commit();

        const uint32_t bbase = sbb + (kt % STAGES) * B_STAGE;
#pragma unroll
        for (int ks = 0; ks < 2; ks++) {
            const uint32_t ca = (uint32_t)(kt * 4 + ks * 2 + lc);
            const uint32_t aoff = ((ca & ~7u) + ((ca & 7u) ^ (uint32_t)sw7)) << 4;
            const uint32_t boff = (uint32_t)(((ks * 2 + lc) ^ bsw) << 4);

            uint32_t af[4][4], bf[2][4];
#pragma unroll
            for (int mt = 0; mt < 4; mt++)
                ldsm4(af[mt][0], af[mt][1], af[mt][2], af[mt][3], aRow[mt] + aoff);
#pragma unroll
            for (int np = 0; np < 2; np++)
                ldsm4(bf[np][0], bf[np][1], bf[np][2], bf[np][3],
                      bbase + bRow[np] + boff);
#pragma unroll
            for (int mt = 0; mt < 4; mt++) {
#pragma unroll
                for (int nt = 0; nt < 4; nt++) {
                    uint32_t bb[2] = { bf[nt >> 1][(nt & 1)],
                                       bf[nt >> 1][(nt & 1) + 2] };
                    mma16816(acc[mt][nt], af[mt], bb);
                }
            }
        }
    }

    // ---- epilogue: bias + fp32 store (warp covers 64 rows x 32 cols) ----
    const int ccol = col0 + wid * 32;
#pragma unroll
    for (int nt = 0; nt < 4; nt++) {
        const int c = ccol + nt * 8 + (lane & 3) * 2;
        const float2 bv = *reinterpret_cast<const float2*>(Bv + c);
#pragma unroll
        for (int mt = 0; mt < 4; mt++) {
            const int r = row0 + mt * 16 + (lane >> 2);
            float2 v0, v1;
            v0.x = acc[mt][nt][0] + bv.x;
            v0.y = acc[mt][nt][1] + bv.y;
            v1.x = acc[mt][nt][2] + bv.x;
            v1.y = acc[mt][nt][3] + bv.y;
            *reinterpret_cast<float2*>(Y + (size_t)r * ND + c) = v0;
            *reinterpret_cast<float2*>(Y + (size_t)(r + 8) * ND + c) = v1;
        }
    }
}

extern "C" void kernel_launch(void* const* d_in, const int* in_sizes, int n_in,
                              void* d_out, int out_size) {
    const float* x = nullptr;
    const float* w = nullptr;
    const float* b = nullptr;
    for (int i = 0; i < n_in; i++) {
        if (in_sizes[i] == BATCH * KD)   x = (const float*)d_in[i];
        else if (in_sizes[i] == ND * KD) w = (const float*)d_in[i];
        else if (in_sizes[i] == ND)      b = (const float*)d_in[i];
    }
    float* out = (float*)d_out;

    cvt_w_kernel<<<(ND * KD / 4) / 256, 256>>>(w);   // ~1 us

    cudaFuncSetAttribute(gemm_fused_kernel,
                         cudaFuncAttributeMaxDynamicSharedMemorySize, SMEM_TOTAL);
    gemm_fused_kernel<<<(BATCH / BM) * (ND / BN), 256, SMEM_TOTAL>>>(x, b, out);
}

// round 10
// speedup vs baseline: 1.1046x; 1.1046x over previous
#include <cuda_runtime.h>
#include <cuda_fp16.h>
#include <cstdint>

static constexpr int BATCH = 65536;
static constexpr int KD    = 512;
static constexpr int ND    = 512;

static constexpr int BM = 128;
static constexpr int BN = 128;
static constexpr int BK = 64;          // 64 fp16 = 128B rows
static constexpr int NKITER = KD / BK; // 8
static constexpr int STAGES = 3;
static constexpr int TILE_BYTES = BM * 128;             // 16 KB
static constexpr int STAGE_BYTES = 2 * TILE_BYTES;      // 32 KB
static constexpr int SMEM_TOTAL = STAGES * STAGE_BYTES; // 96 KB -> 2 CTAs/SM

static constexpr int NBM = BATCH / BM;        // 512 row-blocks
static constexpr int WAVE_BM = 74;            // 296 resident CTAs / 4 bn = 74 bm/wave

// ---------------- scratch + flags (no allocs allowed) ----------------
__device__ __align__(256) __half g_xh[(size_t)BATCH * KD];
__device__ __align__(256) __half g_wh[ND * KD];
__device__ int g_xflag[NBM];

// ---------------- helpers ----------------
static __device__ __forceinline__ uint32_t smem_u32(const void* p) {
    uint32_t a;
    asm("{ .reg .u64 t; cvta.to.shared.u64 t, %1; cvt.u32.u64 %0, t; }"
        : "=r"(a) : "l"(p));
    return a;
}

__device__ __forceinline__ void cp16(uint32_t dst, const void* src) {
    asm volatile("cp.async.cg.shared.global [%0], [%1], 16;"
                 :: "r"(dst), "l"(src) : "memory");
}
__device__ __forceinline__ void cp_commit() {
    asm volatile("cp.async.commit_group;" ::: "memory");
}
template <int N>
__device__ __forceinline__ void cp_wait() {
    asm volatile("cp.async.wait_group %0;" :: "n"(N) : "memory");
}

__device__ __forceinline__ void ldsm4(uint32_t& r0, uint32_t& r1, uint32_t& r2,
                                      uint32_t& r3, uint32_t addr) {
    asm volatile("ldmatrix.sync.aligned.m8n8.x4.shared.b16 {%0,%1,%2,%3}, [%4];"
                 : "=r"(r0), "=r"(r1), "=r"(r2), "=r"(r3) : "r"(addr));
}

__device__ __forceinline__ void mma16816(float* d, const uint32_t* a, const uint32_t* b) {
    asm volatile(
        "mma.sync.aligned.m16n8k16.row.col.f32.f16.f16.f32 "
        "{%0,%1,%2,%3}, {%4,%5,%6,%7}, {%8,%9}, {%0,%1,%2,%3};"
        : "+f"(d[0]), "+f"(d[1]), "+f"(d[2]), "+f"(d[3])
        : "r"(a[0]), "r"(a[1]), "r"(a[2]), "r"(a[3]), "r"(b[0]), "r"(b[1]));
}

// ---------------- W prepass (row-major fp16) + flag clear ----------------
__global__ void __launch_bounds__(256) cvt_w_kernel(const float* __restrict__ s) {
    if (blockIdx.x == 0) {
        g_xflag[threadIdx.x] = 0;
        g_xflag[threadIdx.x + 256] = 0;
    }
    size_t idx = (size_t)blockIdx.x * 256 + threadIdx.x;  // one float4 each
    float4 v = reinterpret_cast<const float4*>(s)[idx];
    __half2 h0 = __floats2half2_rn(v.x, v.y);
    __half2 h1 = __floats2half2_rn(v.z, v.w);
    uint2 u;
    u.x = *reinterpret_cast<uint32_t*>(&h0);
    u.y = *reinterpret_cast<uint32_t*>(&h1);
    reinterpret_cast<uint2*>(g_wh)[idx] = u;
}

// convert one 128-row x block fp32 -> fp16 row-major (256 threads)
__device__ __forceinline__ void convert_block(const float* __restrict__ X,
                                              int blk, int tid) {
    const float4* src = reinterpret_cast<const float4*>(X + (size_t)blk * BM * KD);
    uint2* dst = reinterpret_cast<uint2*>(g_xh + (size_t)blk * BM * KD);
#pragma unroll 4
    for (int i = 0; i < 64; i++) {            // 16384 float4 / 256 threads
        int idx = tid + i * 256;
        float4 v = src[idx];
        __half2 h0 = __floats2half2_rn(v.x, v.y);
        __half2 h1 = __floats2half2_rn(v.z, v.w);
        uint2 u;
        u.x = *reinterpret_cast<uint32_t*>(&h0);
        u.y = *reinterpret_cast<uint32_t*>(&h1);
        dst[idx] = u;
    }
    __threadfence();   // order this thread's stores before the flag release
}

// ---------------- GEMM with in-kernel pipelined x conversion ----------------
// smem tile: 128 rows x 128B; 16B chunk c (0..7) of row r at r*128 + ((c ^ (r&7))<<4)
__global__ void __launch_bounds__(256, 2)
gemm_f16_kernel(const float* __restrict__ X, const float* __restrict__ Bv,
                float* __restrict__ Y) {
    extern __shared__ __align__(1024) char smem[];
    const uint32_t sb = smem_u32(smem);

    const int tid  = threadIdx.x;
    const int wid  = tid >> 5;
    const int lane = tid & 31;

    const int bm = blockIdx.x >> 2;
    const int bn = blockIdx.x & 3;
    const int row0 = bm * BM;
    const int col0 = bn * BN;
    const bool isconv = (bn == 0);

    // wave-0 self-conversion (blocks 0..WAVE_BM-1)
    if (isconv && bm < WAVE_BM) {
        convert_block(X, bm, tid);
        __syncthreads();
        if (tid == 0) atomicExch(&g_xflag[bm], 1);
    } else {
        if (tid == 0) {
            while (atomicAdd(&g_xflag[bm], 0) == 0) { __nanosleep(200); }
        }
        __syncthreads();
    }

    // staging geometry
    const int sr = tid >> 3;
    const int sc = tid & 7;
    const uint32_t sdst = (uint32_t)(sr * 128 + (((uint32_t)sc ^ (uint32_t)(sr & 7)) << 4));
    const __half* Asrc0 = g_xh + (size_t)(row0 + sr) * KD + sc * 8;
    const __half* Bsrc0 = g_wh + (size_t)(col0 + sr) * KD + sc * 8;

    auto stage = [&](int kt, int slot) {
        const uint32_t base = sb + slot * STAGE_BYTES + sdst;
        const __half* as = Asrc0 + kt * BK;
        const __half* bs = Bsrc0 + kt * BK;
#pragma unroll
        for (int i = 0; i < 4; i++)
            cp16(base + i * (32 * 128), as + (size_t)(32 * i) * KD);
#pragma unroll
        for (int i = 0; i < 4; i++)
            cp16(base + TILE_BYTES + i * (32 * 128), bs + (size_t)(32 * i) * KD);
    };

    stage(0, 0); cp_commit();
    stage(1, 1); cp_commit();

    // converter duty: produce NEXT wave's block while cp.async is in flight
    if (isconv && bm + WAVE_BM < NBM) {
        convert_block(X, bm + WAVE_BM, tid);
        __syncthreads();
        if (tid == 0) atomicExch(&g_xflag[bm + WAVE_BM], 1);
    }

    // fragment addressing: warp tile 64x32, 2x4 warp grid
    const int wm = wid & 1;
    const int wn = wid >> 1;
    const uint32_t sw  = (uint32_t)((lane & 7) << 4);
    const uint32_t c16 = (uint32_t)((lane >> 4) << 4);
    uint32_t aRow[4], bRow[2], kx[4];
#pragma unroll
    for (int mt = 0; mt < 4; mt++)
        aRow[mt] = (uint32_t)((wm * 64 + mt * 16 + (lane & 15)) * 128);
#pragma unroll
    for (int np = 0; np < 2; np++)
        bRow[np] = (uint32_t)((wn * 32 + np * 16 + (lane & 15)) * 128);
#pragma unroll
    for (int ks = 0; ks < 4; ks++)
        kx[ks] = (uint32_t)(ks * 32 + c16) ^ sw;

    float acc[4][4][4];
#pragma unroll
    for (int i = 0; i < 4; i++)
#pragma unroll
        for (int j = 0; j < 4; j++)
#pragma unroll
            for (int e = 0; e < 4; e++) acc[i][j][e] = 0.0f;

    for (int kt = 0; kt < NKITER; kt++) {
        cp_wait<1>();
        __syncthreads();
        if (kt + 2 < NKITER) stage(kt + 2, (kt + 2) % STAGES);
        cp_commit();

        const uint32_t abase = sb + (kt % STAGES) * STAGE_BYTES;
        const uint32_t bbase = abase + TILE_BYTES;
#pragma unroll
        for (int ks = 0; ks < 4; ks++) {
            uint32_t af[4][4], bf[2][4];
#pragma unroll
            for (int mt = 0; mt < 4; mt++)
                ldsm4(af[mt][0], af[mt][1], af[mt][2], af[mt][3],
                      abase + aRow[mt] + kx[ks]);
#pragma unroll
            for (int np = 0; np < 2; np++)
                ldsm4(bf[np][0], bf[np][1], bf[np][2], bf[np][3],
                      bbase + bRow[np] + kx[ks]);
#pragma unroll
            for (int mt = 0; mt < 4; mt++) {
#pragma unroll
                for (int nt = 0; nt < 4; nt++) {
                    uint32_t bb[2] = { bf[nt >> 1][(nt & 1)],
                                       bf[nt >> 1][(nt & 1) + 2] };
                    mma16816(acc[mt][nt], af[mt], bb);
                }
            }
        }
    }

    // epilogue: bias + fp32 store
    const int crow = row0 + wm * 64;
    const int ccol = col0 + wn * 32;
#pragma unroll
    for (int nt = 0; nt < 4; nt++) {
        const int c = ccol + nt * 8 + (lane & 3) * 2;
        const float2 bv = *reinterpret_cast<const float2*>(Bv + c);
#pragma unroll
        for (int mt = 0; mt < 4; mt++) {
            const int r = crow + mt * 16 + (lane >> 2);
            float2 v0, v1;
            v0.x = acc[mt][nt][0] + bv.x;
            v0.y = acc[mt][nt][1] + bv.y;
            v1.x = acc[mt][nt][2] + bv.x;
            v1.y = acc[mt][nt][3] + bv.y;
            *reinterpret_cast<float2*>(Y + (size_t)r * ND + c) = v0;
            *reinterpret_cast<float2*>(Y + (size_t)(r + 8) * ND + c) = v1;
        }
    }
}

extern "C" void kernel_launch(void* const* d_in, const int* in_sizes, int n_in,
                              void* d_out, int out_size) {
    const float* x = nullptr;
    const float* w = nullptr;
    const float* b = nullptr;
    for (int i = 0; i < n_in; i++) {
        if (in_sizes[i] == BATCH * KD)   x = (const float*)d_in[i];
        else if (in_sizes[i] == ND * KD) w = (const float*)d_in[i];
        else if (in_sizes[i] == ND)      b = (const float*)d_in[i];
    }
    float* out = (float*)d_out;

    cvt_w_kernel<<<(ND * KD / 4) / 256, 256>>>(w);   // ~1 us, also clears flags

    cudaFuncSetAttribute(gemm_f16_kernel,
                         cudaFuncAttributeMaxDynamicSharedMemorySize, SMEM_TOTAL);
    gemm_f16_kernel<<<(BATCH / BM) * (ND / BN), 256, SMEM_TOTAL>>>(x, b, out);
}

// round 11
// speedup vs baseline: 1.2083x; 1.0939x over previous
#include <cuda_runtime.h>
#include <cuda_fp16.h>
#include <cstdint>

static constexpr int BATCH = 65536;
static constexpr int KD    = 512;
static constexpr int ND    = 512;

static constexpr int BM = 128;
static constexpr int BN = 128;
static constexpr int BK = 64;          // 64 fp16 = 128B rows
static constexpr int NKITER = KD / BK; // 8
static constexpr int STAGES = 3;
static constexpr int TILE_BYTES = BM * 128;             // 16 KB
static constexpr int STAGE_BYTES = 2 * TILE_BYTES;      // 32 KB
static constexpr int SMEM_TOTAL = STAGES * STAGE_BYTES; // 96 KB -> 2 CTAs/SM

static constexpr int NBM = BATCH / BM;        // 512 row-blocks
static constexpr int WAVE_BM = 74;            // 296 resident CTAs / 4 bn

// ---------------- scratch + flags (no allocs allowed) ----------------
__device__ __align__(256) __half g_xh[(size_t)BATCH * KD];
__device__ __align__(256) __half g_wh[ND * KD];
__device__ int g_xflag[NBM];                  // counts 4 slice arrivals

// ---------------- helpers ----------------
static __device__ __forceinline__ uint32_t smem_u32(const void* p) {
    uint32_t a;
    asm("{ .reg .u64 t; cvta.to.shared.u64 t, %1; cvt.u32.u64 %0, t; }"
        : "=r"(a) : "l"(p));
    return a;
}

__device__ __forceinline__ void cp16(uint32_t dst, const void* src) {
    asm volatile("cp.async.cg.shared.global [%0], [%1], 16;"
                 :: "r"(dst), "l"(src) : "memory");
}
__device__ __forceinline__ void cp_commit() {
    asm volatile("cp.async.commit_group;" ::: "memory");
}
template <int N>
__device__ __forceinline__ void cp_wait() {
    asm volatile("cp.async.wait_group %0;" :: "n"(N) : "memory");
}

__device__ __forceinline__ void ldsm4(uint32_t& r0, uint32_t& r1, uint32_t& r2,
                                      uint32_t& r3, uint32_t addr) {
    asm volatile("ldmatrix.sync.aligned.m8n8.x4.shared.b16 {%0,%1,%2,%3}, [%4];"
                 : "=r"(r0), "=r"(r1), "=r"(r2), "=r"(r3) : "r"(addr));
}

__device__ __forceinline__ void mma16816(float* d, const uint32_t* a, const uint32_t* b) {
    asm volatile(
        "mma.sync.aligned.m16n8k16.row.col.f32.f16.f16.f32 "
        "{%0,%1,%2,%3}, {%4,%5,%6,%7}, {%8,%9}, {%0,%1,%2,%3};"
        : "+f"(d[0]), "+f"(d[1]), "+f"(d[2]), "+f"(d[3])
        : "r"(a[0]), "r"(a[1]), "r"(a[2]), "r"(a[3]), "r"(b[0]), "r"(b[1]));
}

// ---------------- W prepass (row-major fp16) + flag clear ----------------
__global__ void __launch_bounds__(256) cvt_w_kernel(const float* __restrict__ s) {
    if (blockIdx.x == 0) {
        g_xflag[threadIdx.x] = 0;
        g_xflag[threadIdx.x + 256] = 0;
    }
    size_t idx = (size_t)blockIdx.x * 256 + threadIdx.x;  // one float4 each
    float4 v = reinterpret_cast<const float4*>(s)[idx];
    __half2 h0 = __floats2half2_rn(v.x, v.y);
    __half2 h1 = __floats2half2_rn(v.z, v.w);
    uint2 u;
    u.x = *reinterpret_cast<uint32_t*>(&h0);
    u.y = *reinterpret_cast<uint32_t*>(&h1);
    reinterpret_cast<uint2*>(g_wh)[idx] = u;
}

// convert one 32-row slice of a 128-row x block (256 threads, 16 float4 each)
__device__ __forceinline__ void convert_slice(const float* __restrict__ X,
                                              int blk, int slice, int tid) {
    const size_t base = ((size_t)blk * BM + (size_t)slice * 32) * KD;
    const float4* src = reinterpret_cast<const float4*>(X + base);
    uint2* dst = reinterpret_cast<uint2*>(g_xh + base);
#pragma unroll 4
    for (int i = 0; i < 16; i++) {            // 4096 float4 / 256 threads
        int idx = tid + i * 256;
        float4 v = src[idx];
        __half2 h0 = __floats2half2_rn(v.x, v.y);
        __half2 h1 = __floats2half2_rn(v.z, v.w);
        uint2 u;
        u.x = *reinterpret_cast<uint32_t*>(&h0);
        u.y = *reinterpret_cast<uint32_t*>(&h1);
        dst[idx] = u;
    }
    __threadfence();   // order stores before the flag arrival
}

// signal one slice done (whole CTA arrived at this point already)
__device__ __forceinline__ void slice_arrive(int blk, int tid) {
    __syncthreads();
    if (tid == 0) atomicAdd(&g_xflag[blk], 1);
}

// ---------------- GEMM with balanced in-kernel pipelined x conversion ----------------
// smem tile: 128 rows x 128B; 16B chunk c (0..7) of row r at r*128 + ((c ^ (r&7))<<4)
__global__ void __launch_bounds__(256, 2)
gemm_f16_kernel(const float* __restrict__ X, const float* __restrict__ Bv,
                float* __restrict__ Y) {
    extern __shared__ __align__(1024) char smem[];
    const uint32_t sb = smem_u32(smem);

    const int tid  = threadIdx.x;
    const int wid  = tid >> 5;
    const int lane = tid & 31;

    const int bm = blockIdx.x >> 2;
    const int bn = blockIdx.x & 3;
    const int row0 = bm * BM;
    const int col0 = bn * BN;

    // wave-0: every CTA converts slice bn of its OWN block first
    if (bm < WAVE_BM) {
        convert_slice(X, bm, bn, tid);
        slice_arrive(bm, tid);
    }
    // wait for own block fully converted (4 slices)
    if (tid == 0) {
        while (atomicAdd(&g_xflag[bm], 0) != 4) { __nanosleep(200); }
    }
    __syncthreads();

    // staging geometry
    const int sr = tid >> 3;
    const int sc = tid & 7;
    const uint32_t sdst = (uint32_t)(sr * 128 + (((uint32_t)sc ^ (uint32_t)(sr & 7)) << 4));
    const __half* Asrc0 = g_xh + (size_t)(row0 + sr) * KD + sc * 8;
    const __half* Bsrc0 = g_wh + (size_t)(col0 + sr) * KD + sc * 8;

    auto stage = [&](int kt, int slot) {
        const uint32_t base = sb + slot * STAGE_BYTES + sdst;
        const __half* as = Asrc0 + kt * BK;
        const __half* bs = Bsrc0 + kt * BK;
#pragma unroll
        for (int i = 0; i < 4; i++)
            cp16(base + i * (32 * 128), as + (size_t)(32 * i) * KD);
#pragma unroll
        for (int i = 0; i < 4; i++)
            cp16(base + TILE_BYTES + i * (32 * 128), bs + (size_t)(32 * i) * KD);
    };

    stage(0, 0); cp_commit();
    stage(1, 1); cp_commit();

    // converter duty: slice bn of NEXT wave's block, overlapped with cp.async
    if (bm + WAVE_BM < NBM) {
        convert_slice(X, bm + WAVE_BM, bn, tid);
        slice_arrive(bm + WAVE_BM, tid);
    }

    // fragment addressing: warp tile 64x32, 2x4 warp grid
    const int wm = wid & 1;
    const int wn = wid >> 1;
    const uint32_t sw  = (uint32_t)((lane & 7) << 4);
    const uint32_t c16 = (uint32_t)((lane >> 4) << 4);
    uint32_t aRow[4], bRow[2], kx[4];
#pragma unroll
    for (int mt = 0; mt < 4; mt++)
        aRow[mt] = (uint32_t)((wm * 64 + mt * 16 + (lane & 15)) * 128);
#pragma unroll
    for (int np = 0; np < 2; np++)
        bRow[np] = (uint32_t)((wn * 32 + np * 16 + (lane & 15)) * 128);
#pragma unroll
    for (int ks = 0; ks < 4; ks++)
        kx[ks] = (uint32_t)(ks * 32 + c16) ^ sw;

    float acc[4][4][4];
#pragma unroll
    for (int i = 0; i < 4; i++)
#pragma unroll
        for (int j = 0; j < 4; j++)
#pragma unroll
            for (int e = 0; e < 4; e++) acc[i][j][e] = 0.0f;

    for (int kt = 0; kt < NKITER; kt++) {
        cp_wait<1>();
        __syncthreads();
        if (kt + 2 < NKITER) stage(kt + 2, (kt + 2) % STAGES);
        cp_commit();

        const uint32_t abase = sb + (kt % STAGES) * STAGE_BYTES;
        const uint32_t bbase = abase + TILE_BYTES;
#pragma unroll
        for (int ks = 0; ks < 4; ks++) {
            uint32_t af[4][4], bf[2][4];
#pragma unroll
            for (int mt = 0; mt < 4; mt++)
                ldsm4(af[mt][0], af[mt][1], af[mt][2], af[mt][3],
                      abase + aRow[mt] + kx[ks]);
#pragma unroll
            for (int np = 0; np < 2; np++)
                ldsm4(bf[np][0], bf[np][1], bf[np][2], bf[np][3],
                      bbase + bRow[np] + kx[ks]);
#pragma unroll
            for (int mt = 0; mt < 4; mt++) {
#pragma unroll
                for (int nt = 0; nt < 4; nt++) {
                    uint32_t bb[2] = { bf[nt >> 1][(nt & 1)],
                                       bf[nt >> 1][(nt & 1) + 2] };
                    mma16816(acc[mt][nt], af[mt], bb);
                }
            }
        }
    }

    // epilogue: bias + fp32 store
    const int crow = row0 + wm * 64;
    const int ccol = col0 + wn * 32;
#pragma unroll
    for (int nt = 0; nt < 4; nt++) {
        const int c = ccol + nt * 8 + (lane & 3) * 2;
        const float2 bv = *reinterpret_cast<const float2*>(Bv + c);
#pragma unroll
        for (int mt = 0; mt < 4; mt++) {
            const int r = crow + mt * 16 + (lane >> 2);
            float2 v0, v1;
            v0.x = acc[mt][nt][0] + bv.x;
            v0.y = acc[mt][nt][1] + bv.y;
            v1.x = acc[mt][nt][2] + bv.x;
            v1.y = acc[mt][nt][3] + bv.y;
            *reinterpret_cast<float2*>(Y + (size_t)r * ND + c) = v0;
            *reinterpret_cast<float2*>(Y + (size_t)(r + 8) * ND + c) = v1;
        }
    }
}

extern "C" void kernel_launch(void* const* d_in, const int* in_sizes, int n_in,
                              void* d_out, int out_size) {
    const float* x = nullptr;
    const float* w = nullptr;
    const float* b = nullptr;
    for (int i = 0; i < n_in; i++) {
        if (in_sizes[i] == BATCH * KD)   x = (const float*)d_in[i];
        else if (in_sizes[i] == ND * KD) w = (const float*)d_in[i];
        else if (in_sizes[i] == ND)      b = (const float*)d_in[i];
    }
    float* out = (float*)d_out;

    cvt_w_kernel<<<(ND * KD / 4) / 256, 256>>>(w);   // ~1 us, also clears flags

    cudaFuncSetAttribute(gemm_f16_kernel,
                         cudaFuncAttributeMaxDynamicSharedMemorySize, SMEM_TOTAL);
    gemm_f16_kernel<<<(BATCH / BM) * (ND / BN), 256, SMEM_TOTAL>>>(x, b, out);
}